// round 8
// baseline (speedup 1.0000x reference)
#include <cuda_runtime.h>
#include <cuda_bf16.h>

#define BATCH 256

// zero-value basis constants: v=0 -> t=4.5, i0=4, u=0.5
#define ZB2 (1.f/48.f)
#define ZB3 (23.f/48.f)

typedef unsigned long long u64;

// ---------------- packed f32x2 helpers (Blackwell FFMA2) -------------------
__device__ __forceinline__ u64 pack_dup(float x) {
    u64 r; asm("mov.b64 %0, {%1, %1};" : "=l"(r) : "f"(x)); return r;
}
__device__ __forceinline__ void unpack2(u64 v, float& x, float& y) {
    asm("mov.b64 {%0, %1}, %2;" : "=f"(x), "=f"(y) : "l"(v));
}
__device__ __forceinline__ void ffma2(u64& d, u64 a, u64 b) {
    asm("fma.rn.f32x2 %0, %1, %2, %0;" : "+l"(d) : "l"(a), "l"(b));
}

// ---------------- scratch (static device globals: allocation-free) ----------
__device__ float d_bas1 [BATCH * 3  * 34 * 34 * 8];
__device__ float d_conv1[BATCH * 8  * 32 * 32];
__device__ float d_bas2 [BATCH * 8  * 18 * 18 * 8];
__device__ float d_conv2[BATCH * 16 * 16 * 16];
__device__ float d_bas3 [BATCH * 16 * 10 * 10 * 8];
__device__ float d_conv3[BATCH * 32 * 8  * 8];
__device__ float d_pool3[BATCH * 32 * 4  * 4];
// combined weights: [n_otile][F][7 slots][TILE ch], slot0=base_w, 1..6=spline*scaler
__device__ float d_sw1[1 * 27  * 7 * 8];   // TILE=8
__device__ float d_sw2[2 * 72  * 7 * 8];   // TILE=8
__device__ float d_sw3[8 * 144 * 7 * 4];   // TILE=4
__device__ float d_wt [512 * 100];         // transposed lin_w: [k][o]

// ---------------- basis evaluation (once per input element) ---------------
__device__ __forceinline__ void basis8(float v, float* sv) {
    sv[0] = v * (1.f / (1.f + __expf(-v)));          // silu
    float t  = (v + 3.f) * 1.5f;
    bool valid = (t >= 0.f) && (t < 9.f);
    float fi = floorf(t);
    int   i0 = (int)fi;
    float u  = t - fi;
    float u2 = u * u, u3 = u2 * u;
    float q3 = u3 * (1.f / 6.f);
    float q2 = ((3.f * u2 - 3.f * u3) + 3.f * u + 1.f) * (1.f / 6.f);
    float q1 = (3.f * u3 - 6.f * u2 + 4.f) * (1.f / 6.f);
    float iu = 1.f - u;
    float q0 = iu * iu * iu * (1.f / 6.f);
    if (!valid) { q0 = q1 = q2 = q3 = 0.f; i0 = -1000; }
#pragma unroll
    for (int m = 0; m < 6; m++) {
        int d = i0 - m;
        sv[1 + m] = (d == 0) ? q3 : (d == 1) ? q2 : (d == 2) ? q1
                  : (d == 3) ? q0 : 0.f;
    }
    sv[7] = 0.f;
}

__device__ __forceinline__ void store_bas(float* dst, const float* sv) {
    reinterpret_cast<float4*>(dst)[0] = make_float4(sv[0], sv[1], sv[2], sv[3]);
    reinterpret_cast<float4*>(dst)[1] = make_float4(sv[4], sv[5], sv[6], sv[7]);
}

// ---------------- layer-1 basis: x [B,C,HW,HW] -> bas [B,C,P,P,8] ----------
template<int C, int HW>
__global__ void basis_in_kernel(const float* __restrict__ X, float* __restrict__ BAS) {
    constexpr int P = HW + 2;
    int idx = blockIdx.x * blockDim.x + threadIdx.x;
    if (idx >= BATCH * C * P * P) return;
    int xp = idx % P;
    int yp = (idx / P) % P;
    int bc = idx / (P * P);
    float sv[8];
    if (xp == 0 || xp == P - 1 || yp == 0 || yp == P - 1) {
        sv[0] = 0.f; sv[1] = 0.f; sv[2] = ZB2; sv[3] = ZB3;
        sv[4] = ZB3; sv[5] = ZB2; sv[6] = 0.f; sv[7] = 0.f;
    } else {
        float v = X[((long)bc * HW + (yp - 1)) * HW + (xp - 1)];
        basis8(v, sv);
    }
    store_bas(BAS + (long)idx * 8, sv);
}

// ---------- fused maxpool(2x2) + basis: conv out -> next-layer basis -------
template<int C, int HWI>
__global__ void pool_basis_kernel(const float* __restrict__ X, float* __restrict__ BAS) {
    constexpr int HWO = HWI / 2;
    constexpr int P   = HWO + 2;
    int idx = blockIdx.x * blockDim.x + threadIdx.x;
    if (idx >= BATCH * C * P * P) return;
    int xp = idx % P;
    int yp = (idx / P) % P;
    int bc = idx / (P * P);
    float sv[8];
    if (xp == 0 || xp == P - 1 || yp == 0 || yp == P - 1) {
        sv[0] = 0.f; sv[1] = 0.f; sv[2] = ZB2; sv[3] = ZB3;
        sv[4] = ZB3; sv[5] = ZB2; sv[6] = 0.f; sv[7] = 0.f;
    } else {
        const float* Xp = X + ((long)bc * HWI + (yp - 1) * 2) * HWI + (xp - 1) * 2;
        float v = fmaxf(fmaxf(Xp[0], Xp[1]), fmaxf(Xp[HWI], Xp[HWI + 1]));
        basis8(v, sv);
    }
    store_bas(BAS + (long)idx * 8, sv);
}

// ---------------- fused KAN 3x3 conv over precomputed basis ----------------
// One thread = FOUR adjacent x positions x one tile of TILE output channels.
// Each broadcast weight LDS.128 feeds 4 positions (POS=4 halves LDS count vs
// POS=2). Channel pairs accumulate in packed f32x2 (FFMA2). ZB halo -> no
// bounds checks.
template<int C, int HW, int NTILE, int TILE, int BLK>
__global__ void __launch_bounds__(BLK)
conv_kan_kernel(const float* __restrict__ BAS,   // [B][C][P][P][8]
                const float* __restrict__ SW,    // [NTILE][F][7][TILE]
                float* __restrict__ Y) {         // [B][NTILE*TILE][HW][HW]
    constexpr int F   = C * 9;
    constexpr int O   = NTILE * TILE;
    constexpr int P   = HW + 2;
    constexpr int HX  = HW / 4;
    constexpr int WPF = 7 * TILE;          // weights per feature
    constexpr int NP  = TILE / 2;          // channel pairs
    __shared__ __align__(16) float sw[F * WPF];

    const float* gsw = SW + blockIdx.y * (F * WPF);
    for (int i = threadIdx.x; i < F * WPF / 4; i += BLK)
        reinterpret_cast<float4*>(sw)[i] = reinterpret_cast<const float4*>(gsw)[i];
    __syncthreads();

    int p = blockIdx.x * BLK + threadIdx.x;
    if (p >= BATCH * HW * HX) return;
    int x0 = (p % HX) * 4;
    int y  = (p / HX) % HW;
    int b  = p / (HX * HW);

    u64 acc2[4][NP];                        // [pos][channel pair]
#pragma unroll
    for (int k = 0; k < 4; k++)
#pragma unroll
        for (int q = 0; q < NP; q++) acc2[k][q] = 0ull;

    const float* Bb = BAS + (long)b * C * P * P * 8;
    for (int c = 0; c < C; c++) {
        const float* Bc = Bb + c * P * P * 8;
#pragma unroll
        for (int ky = 0; ky < 3; ky++) {
            const float* rp = Bc + (((y + ky) * P) + x0) * 8;
            float bvf[6][8];                // basis vecs for padded x0..x0+5
#pragma unroll
            for (int i = 0; i < 6; i++) {
                float4 t0 = *reinterpret_cast<const float4*>(rp + i * 8);
                float4 t1 = *reinterpret_cast<const float4*>(rp + i * 8 + 4);
                bvf[i][0] = t0.x; bvf[i][1] = t0.y; bvf[i][2] = t0.z; bvf[i][3] = t0.w;
                bvf[i][4] = t1.x; bvf[i][5] = t1.y; bvf[i][6] = t1.z; bvf[i][7] = t1.w;
            }
            const float* wbase = sw + (c * 9 + ky * 3) * WPF;
#pragma unroll
            for (int kx = 0; kx < 3; kx++) {
                const float* wp = wbase + kx * WPF;
#pragma unroll
                for (int s = 0; s < 7; s++) {
                    ulonglong2 wA = *reinterpret_cast<const ulonglong2*>(wp + s * TILE);
                    ulonglong2 wB;
                    if (TILE == 8)
                        wB = *reinterpret_cast<const ulonglong2*>(wp + s * TILE + 4);
#pragma unroll
                    for (int pos = 0; pos < 4; pos++) {
                        u64 sp = pack_dup(bvf[kx + pos][s]);
                        ffma2(acc2[pos][0], sp, wA.x);
                        ffma2(acc2[pos][1], sp, wA.y);
                        if (TILE == 8) {
                            ffma2(acc2[pos][2], sp, wB.x);
                            ffma2(acc2[pos][3], sp, wB.y);
                        }
                    }
                }
            }
        }
    }

    float* Yp = Y + (((long)b * O + blockIdx.y * TILE) * HW + y) * HW + x0;
#pragma unroll
    for (int q = 0; q < NP; q++) {
        float a[4], bb[4];
#pragma unroll
        for (int pos = 0; pos < 4; pos++) unpack2(acc2[pos][q], a[pos], bb[pos]);
        *reinterpret_cast<float4*>(Yp + (2 * q) * HW * HW)     = make_float4(a[0], a[1], a[2], a[3]);
        *reinterpret_cast<float4*>(Yp + (2 * q + 1) * HW * HW) = make_float4(bb[0], bb[1], bb[2], bb[3]);
    }
}

// ---------------- plain 2x2 maxpool (final layer only) --------------------
__global__ void maxpool_kernel(const float* __restrict__ X, float* __restrict__ Y,
                               int total_out, int HW_in) {
    int idx = blockIdx.x * blockDim.x + threadIdx.x;
    if (idx >= total_out) return;
    int ho = HW_in >> 1;
    int xo = idx % ho;
    int yo = (idx / ho) % ho;
    int bo = idx / (ho * ho);
    const float* Xp = X + ((long)bo * HW_in + yo * 2) * HW_in + xo * 2;
    Y[idx] = fmaxf(fmaxf(Xp[0], Xp[1]), fmaxf(Xp[HW_in], Xp[HW_in + 1]));
}

// ---------------- merged weight prep --------------------------------------
__device__ __forceinline__ void prep_sw_elem(const float* base_w, const float* spline_w,
                                             const float* scaler, float* sw,
                                             int idx, int F, int TILE) {
    int slot = idx % 7;
    int f    = (idx / 7) % F;
    int o    = idx / (7 * F);
    float v;
    if (slot == 0) v = base_w[o * F + f];
    else           v = spline_w[(o * F + f) * 6 + (slot - 1)] * scaler[o * F + f];
    int tile = o / TILE, j = o % TILE;
    sw[((tile * F + f) * 7 + slot) * TILE + j] = v;
}

__global__ void prep_all_kernel(const float* __restrict__ c1_bw, const float* __restrict__ c1_sw,
                                const float* __restrict__ c1_sc,
                                const float* __restrict__ c2_bw, const float* __restrict__ c2_sw,
                                const float* __restrict__ c2_sc,
                                const float* __restrict__ c3_bw, const float* __restrict__ c3_sw,
                                const float* __restrict__ c3_sc,
                                const float* __restrict__ lin_w,
                                float* __restrict__ sw1, float* __restrict__ sw2,
                                float* __restrict__ sw3, float* __restrict__ wt) {
    const int N1 = 8 * 27 * 7, N2 = 16 * 72 * 7, N3 = 32 * 144 * 7, NW = 100 * 512;
    int idx = blockIdx.x * blockDim.x + threadIdx.x;
    if (idx < N1)                    prep_sw_elem(c1_bw, c1_sw, c1_sc, sw1, idx, 27, 8);
    else if (idx < N1 + N2)          prep_sw_elem(c2_bw, c2_sw, c2_sc, sw2, idx - N1, 72, 8);
    else if (idx < N1 + N2 + N3)     prep_sw_elem(c3_bw, c3_sw, c3_sc, sw3, idx - N1 - N2, 144, 4);
    else if (idx < N1 + N2 + N3 + NW) {
        int i = idx - N1 - N2 - N3;
        int o = i / 512, k = i % 512;
        wt[k * 100 + o] = lin_w[i];
    }
}

// ---------------- final linear: [256,512] @ [512,100]^T + b ----------------
__global__ void __launch_bounds__(128)
linear_kernel(const float* __restrict__ X, const float* __restrict__ WT,
              const float* __restrict__ bias, float* __restrict__ out) {
    __shared__ float xs[4][512];
    int b0 = blockIdx.x * 4;
    for (int i = threadIdx.x; i < 4 * 512; i += blockDim.x)
        xs[i / 512][i % 512] = X[(long)b0 * 512 + i];
    __syncthreads();
    int o = threadIdx.x;
    if (o >= 100) return;
    float acc0 = 0.f, acc1 = 0.f, acc2 = 0.f, acc3 = 0.f;
    for (int k = 0; k < 512; k++) {
        float w = WT[k * 100 + o];
        acc0 = fmaf(xs[0][k], w, acc0);
        acc1 = fmaf(xs[1][k], w, acc1);
        acc2 = fmaf(xs[2][k], w, acc2);
        acc3 = fmaf(xs[3][k], w, acc3);
    }
    float bb = bias[o];
    out[(b0 + 0) * 100 + o] = acc0 + bb;
    out[(b0 + 1) * 100 + o] = acc1 + bb;
    out[(b0 + 2) * 100 + o] = acc2 + bb;
    out[(b0 + 3) * 100 + o] = acc3 + bb;
}

// ---------------- launch ---------------------------------------------------
extern "C" void kernel_launch(void* const* d_in, const int* in_sizes, int n_in,
                              void* d_out, int out_size) {
    const float* x     = (const float*)d_in[0];
    const float* c1_bw = (const float*)d_in[1];
    const float* c1_sw = (const float*)d_in[2];
    const float* c1_sc = (const float*)d_in[3];
    const float* c2_bw = (const float*)d_in[4];
    const float* c2_sw = (const float*)d_in[5];
    const float* c2_sc = (const float*)d_in[6];
    const float* c3_bw = (const float*)d_in[7];
    const float* c3_sw = (const float*)d_in[8];
    const float* c3_sc = (const float*)d_in[9];
    const float* lin_w = (const float*)d_in[10];
    const float* lin_b = (const float*)d_in[11];
    float* out = (float*)d_out;

    float *p_bas1, *p_conv1, *p_bas2, *p_conv2, *p_bas3, *p_conv3, *p_pool3;
    float *p_sw1, *p_sw2, *p_sw3, *p_wt;
    cudaGetSymbolAddress((void**)&p_bas1,  d_bas1);
    cudaGetSymbolAddress((void**)&p_conv1, d_conv1);
    cudaGetSymbolAddress((void**)&p_bas2,  d_bas2);
    cudaGetSymbolAddress((void**)&p_conv2, d_conv2);
    cudaGetSymbolAddress((void**)&p_bas3,  d_bas3);
    cudaGetSymbolAddress((void**)&p_conv3, d_conv3);
    cudaGetSymbolAddress((void**)&p_pool3, d_pool3);
    cudaGetSymbolAddress((void**)&p_sw1,   d_sw1);
    cudaGetSymbolAddress((void**)&p_sw2,   d_sw2);
    cudaGetSymbolAddress((void**)&p_sw3,   d_sw3);
    cudaGetSymbolAddress((void**)&p_wt,    d_wt);

    // merged weight prep (1 launch)
    {
        int total = 8*27*7 + 16*72*7 + 32*144*7 + 100*512;
        prep_all_kernel<<<(total + 255) / 256, 256>>>(
            c1_bw, c1_sw, c1_sc, c2_bw, c2_sw, c2_sc, c3_bw, c3_sw, c3_sc,
            lin_w, p_sw1, p_sw2, p_sw3, p_wt);
    }
    // layer 1: conv [256,8,32,32], POS=4 -> 65536 threads
    {
        int n = BATCH * 3 * 34 * 34;
        basis_in_kernel<3, 32><<<(n + 255) / 256, 256>>>(x, p_bas1);
        dim3 grid(BATCH * 32 * 8 / 128, 1);
        conv_kan_kernel<3, 32, 1, 8, 128><<<grid, 128>>>(p_bas1, p_sw1, p_conv1);
        int m = BATCH * 8 * 18 * 18;
        pool_basis_kernel<8, 32><<<(m + 255) / 256, 256>>>(p_conv1, p_bas2);
    }
    // layer 2: conv [256,16,16,16], POS=4, block 64
    {
        dim3 grid(BATCH * 16 * 4 / 64, 2);
        conv_kan_kernel<8, 16, 2, 8, 64><<<grid, 64>>>(p_bas2, p_sw2, p_conv2);
        int m = BATCH * 16 * 10 * 10;
        pool_basis_kernel<16, 16><<<(m + 255) / 256, 256>>>(p_conv2, p_bas3);
    }
    // layer 3: conv [256,32,8,8], POS=4, channel-tile 4, block 64
    {
        dim3 grid(BATCH * 8 * 2 / 64, 8);
        conv_kan_kernel<16, 8, 8, 4, 64><<<grid, 64>>>(p_bas3, p_sw3, p_conv3);
        int n = BATCH * 32 * 4 * 4;
        maxpool_kernel<<<(n + 255) / 256, 256>>>(p_conv3, p_pool3, n, 8);
    }
    // linear
    linear_kernel<<<BATCH / 4, 128>>>(p_pool3, p_wt, lin_b, out);
}

// round 9
// speedup vs baseline: 1.2462x; 1.2462x over previous
#include <cuda_runtime.h>
#include <cuda_bf16.h>

#define BATCH 256

// zero-value basis constants: v=0 -> t=4.5, i0=4, u=0.5
#define ZB2 (1.f/48.f)
#define ZB3 (23.f/48.f)

typedef unsigned long long u64;

// ---------------- packed f32x2 helpers (Blackwell FFMA2) -------------------
__device__ __forceinline__ u64 pack_dup(float x) {
    u64 r; asm("mov.b64 %0, {%1, %1};" : "=l"(r) : "f"(x)); return r;
}
__device__ __forceinline__ void unpack2(u64 v, float& x, float& y) {
    asm("mov.b64 {%0, %1}, %2;" : "=f"(x), "=f"(y) : "l"(v));
}
__device__ __forceinline__ void ffma2(u64& d, u64 a, u64 b) {
    asm("fma.rn.f32x2 %0, %1, %2, %0;" : "+l"(d) : "l"(a), "l"(b));
}

// ---------------- scratch (static device globals: allocation-free) ----------
__device__ float d_bas1 [BATCH * 3  * 34 * 34 * 8];
__device__ float d_bas2 [BATCH * 8  * 18 * 18 * 8];
__device__ float d_bas3 [BATCH * 16 * 10 * 10 * 8];
__device__ float d_pool3[BATCH * 32 * 4  * 4];
// combined weights: [n_otile][F][7 slots][8 ch], slot0=base_w, 1..6=spline*scaler
__device__ float d_sw1[1 * 27  * 7 * 8];
__device__ float d_sw2[2 * 72  * 7 * 8];
__device__ float d_sw3[4 * 144 * 7 * 8];
__device__ float d_wt [512 * 100];         // transposed lin_w: [k][o]

// ---------------- basis evaluation -----------------------------------------
__device__ __forceinline__ void basis8(float v, float* sv) {
    sv[0] = v * (1.f / (1.f + __expf(-v)));          // silu
    float t  = (v + 3.f) * 1.5f;
    bool valid = (t >= 0.f) && (t < 9.f);
    float fi = floorf(t);
    int   i0 = (int)fi;
    float u  = t - fi;
    float u2 = u * u, u3 = u2 * u;
    float q3 = u3 * (1.f / 6.f);
    float q2 = ((3.f * u2 - 3.f * u3) + 3.f * u + 1.f) * (1.f / 6.f);
    float q1 = (3.f * u3 - 6.f * u2 + 4.f) * (1.f / 6.f);
    float iu = 1.f - u;
    float q0 = iu * iu * iu * (1.f / 6.f);
    if (!valid) { q0 = q1 = q2 = q3 = 0.f; i0 = -1000; }
#pragma unroll
    for (int m = 0; m < 6; m++) {
        int d = i0 - m;
        sv[1 + m] = (d == 0) ? q3 : (d == 1) ? q2 : (d == 2) ? q1
                  : (d == 3) ? q0 : 0.f;
    }
    sv[7] = 0.f;
}

__device__ __forceinline__ void store_bas(float* dst, const float* sv) {
    reinterpret_cast<float4*>(dst)[0] = make_float4(sv[0], sv[1], sv[2], sv[3]);
    reinterpret_cast<float4*>(dst)[1] = make_float4(sv[4], sv[5], sv[6], sv[7]);
}

// ---------------- layer-1 basis: x [B,C,HW,HW] -> bas [B,C,P,P,8] ----------
template<int C, int HW>
__global__ void basis_in_kernel(const float* __restrict__ X, float* __restrict__ BAS) {
    constexpr int P = HW + 2;
    int idx = blockIdx.x * blockDim.x + threadIdx.x;
    if (idx >= BATCH * C * P * P) return;
    int xp = idx % P;
    int yp = (idx / P) % P;
    int bc = idx / (P * P);
    float sv[8];
    if (xp == 0 || xp == P - 1 || yp == 0 || yp == P - 1) {
        sv[0] = 0.f; sv[1] = 0.f; sv[2] = ZB2; sv[3] = ZB3;
        sv[4] = ZB3; sv[5] = ZB2; sv[6] = 0.f; sv[7] = 0.f;
    } else {
        float v = X[((long)bc * HW + (yp - 1)) * HW + (xp - 1)];
        basis8(v, sv);
    }
    store_bas(BAS + (long)idx * 8, sv);
}

// -------- fused KAN conv3x3 + maxpool2x2 + next-layer basis ----------------
// Thread = x-pool-pair (x0=2k, x0+1) at row y, tile of 8 output channels.
// The vertical pool partner (row y^1) is exactly HX lanes away in the same
// warp (x-major mapping, HX in {16,8,4}) -> one shfl_xor completes the 2x2
// max. Even-row lanes emit basis8(pooled) into the next layer's halo'd
// basis array (WRITE_BASIS) or the raw pooled value (layer 3).
template<int C, int HW, int NTILE, bool WRITE_BASIS>
__global__ void __launch_bounds__(256)
convpool_kernel(const float* __restrict__ BAS,   // [B][C][P][P][8]
                const float* __restrict__ SW,    // [NTILE][F][7][8]
                float* __restrict__ OUT) {       // basis[B][O][Po][Po][8] or pool[B][O][HW/2][HW/2]
    constexpr int F   = C * 9;
    constexpr int O   = NTILE * 8;
    constexpr int P   = HW + 2;
    constexpr int HX  = HW / 2;
    constexpr int HWO = HW / 2;
    constexpr int PO  = HWO + 2;
    __shared__ __align__(16) float sw[F * 56];

    const float* gsw = SW + blockIdx.y * (F * 56);
    for (int i = threadIdx.x; i < F * 56 / 4; i += 256)
        reinterpret_cast<float4*>(sw)[i] = reinterpret_cast<const float4*>(gsw)[i];
    __syncthreads();

    int p = blockIdx.x * 256 + threadIdx.x;
    int x0 = (p % HX) * 2;
    int y  = (p / HX) % HW;
    int b  = p / (HX * HW);

    u64 acc2[8];                      // [pos0 pairs 01,23,45,67 | pos1 pairs]
#pragma unroll
    for (int j = 0; j < 8; j++) acc2[j] = 0ull;

    const float* Bb = BAS + (long)b * C * P * P * 8;
    for (int c = 0; c < C; c++) {
        const float* Bc = Bb + c * P * P * 8;
#pragma unroll
        for (int ky = 0; ky < 3; ky++) {
            const float* rp = Bc + (((y + ky) * P) + x0) * 8;
            float bvf[4][8];          // basis vecs for padded x0..x0+3
#pragma unroll
            for (int i = 0; i < 4; i++) {
                float4 t0 = *reinterpret_cast<const float4*>(rp + i * 8);
                float4 t1 = *reinterpret_cast<const float4*>(rp + i * 8 + 4);
                bvf[i][0] = t0.x; bvf[i][1] = t0.y; bvf[i][2] = t0.z; bvf[i][3] = t0.w;
                bvf[i][4] = t1.x; bvf[i][5] = t1.y; bvf[i][6] = t1.z; bvf[i][7] = t1.w;
            }
            const float* wbase = sw + (c * 9 + ky * 3) * 56;
#pragma unroll
            for (int kx = 0; kx < 3; kx++) {
                const float* wp = wbase + kx * 56;
#pragma unroll
                for (int s = 0; s < 7; s++) {
                    ulonglong2 w01 = *reinterpret_cast<const ulonglong2*>(wp + s * 8);
                    ulonglong2 w23 = *reinterpret_cast<const ulonglong2*>(wp + s * 8 + 4);
                    u64 sp0 = pack_dup(bvf[kx][s]);
                    u64 sp1 = pack_dup(bvf[kx + 1][s]);
                    ffma2(acc2[0], sp0, w01.x);
                    ffma2(acc2[1], sp0, w01.y);
                    ffma2(acc2[2], sp0, w23.x);
                    ffma2(acc2[3], sp0, w23.y);
                    ffma2(acc2[4], sp1, w01.x);
                    ffma2(acc2[5], sp1, w01.y);
                    ffma2(acc2[6], sp1, w23.x);
                    ffma2(acc2[7], sp1, w23.y);
                }
            }
        }
    }

    // horizontal pool within thread, vertical pool via shfl_xor(HX)
    float hm[8];
#pragma unroll
    for (int q = 0; q < 4; q++) {
        float p0a, p0b, p1a, p1b;
        unpack2(acc2[q],     p0a, p0b);
        unpack2(acc2[4 + q], p1a, p1b);
        hm[2 * q]     = fmaxf(p0a, p1a);
        hm[2 * q + 1] = fmaxf(p0b, p1b);
    }
#pragma unroll
    for (int j = 0; j < 8; j++) {
        float other = __shfl_xor_sync(0xffffffffu, hm[j], HX);
        hm[j] = fmaxf(hm[j], other);
    }

    if (((p / HX) & 1) == 0) {        // even conv row -> owns the pool cell
        int xo = p % HX;              // = x0/2
        int yo = y >> 1;
        if (WRITE_BASIS) {
#pragma unroll
            for (int j = 0; j < 8; j++) {
                float sv[8];
                basis8(hm[j], sv);
                int ch = blockIdx.y * 8 + j;
                long bc = (long)b * O + ch;
                store_bas(OUT + ((bc * PO + (yo + 1)) * PO + (xo + 1)) * 8, sv);
            }
        } else {
#pragma unroll
            for (int j = 0; j < 8; j++) {
                int ch = blockIdx.y * 8 + j;
                OUT[(((long)b * O + ch) * HWO + yo) * HWO + xo] = hm[j];
            }
        }
    }
}

// ---------------- merged weight prep + halo fill ---------------------------
__device__ __forceinline__ void prep_sw_elem(const float* base_w, const float* spline_w,
                                             const float* scaler, float* sw,
                                             int idx, int F) {
    int slot = idx % 7;
    int f    = (idx / 7) % F;
    int o    = idx / (7 * F);
    float v;
    if (slot == 0) v = base_w[o * F + f];
    else           v = spline_w[(o * F + f) * 6 + (slot - 1)] * scaler[o * F + f];
    int tile = o >> 3, j = o & 7;
    sw[((tile * F + f) * 7 + slot) * 8 + j] = v;
}

__device__ __forceinline__ void halo_fill(float* bas, int i, int P) {
    int hc  = 4 * P - 4;
    int img = i / hc;
    int k   = i % hc;
    int xp, yp;
    if (k < P)          { yp = 0;      xp = k; }
    else if (k < 2 * P) { yp = P - 1;  xp = k - P; }
    else {
        int r = k - 2 * P;
        yp = 1 + (r >> 1);
        xp = (r & 1) ? (P - 1) : 0;
    }
    float sv[8] = {0.f, 0.f, ZB2, ZB3, ZB3, ZB2, 0.f, 0.f};
    store_bas(bas + (((long)img * P + yp) * P + xp) * 8, sv);
}

__global__ void prep_all_kernel(const float* __restrict__ c1_bw, const float* __restrict__ c1_sw,
                                const float* __restrict__ c1_sc,
                                const float* __restrict__ c2_bw, const float* __restrict__ c2_sw,
                                const float* __restrict__ c2_sc,
                                const float* __restrict__ c3_bw, const float* __restrict__ c3_sw,
                                const float* __restrict__ c3_sc,
                                const float* __restrict__ lin_w,
                                float* __restrict__ sw1, float* __restrict__ sw2,
                                float* __restrict__ sw3, float* __restrict__ wt,
                                float* __restrict__ bas2, float* __restrict__ bas3) {
    const int N1 = 8 * 27 * 7, N2 = 16 * 72 * 7, N3 = 32 * 144 * 7, NW = 100 * 512;
    const int H2 = BATCH * 8  * (4 * 18 - 4);   // bas2 halo cells
    const int H3 = BATCH * 16 * (4 * 10 - 4);   // bas3 halo cells
    int idx = blockIdx.x * blockDim.x + threadIdx.x;
    int e1 = N1, e2 = e1 + N2, e3 = e2 + N3, e4 = e3 + NW, e5 = e4 + H2, e6 = e5 + H3;
    if (idx < e1)       prep_sw_elem(c1_bw, c1_sw, c1_sc, sw1, idx, 27);
    else if (idx < e2)  prep_sw_elem(c2_bw, c2_sw, c2_sc, sw2, idx - e1, 72);
    else if (idx < e3)  prep_sw_elem(c3_bw, c3_sw, c3_sc, sw3, idx - e2, 144);
    else if (idx < e4) {
        int i = idx - e3;
        int o = i / 512, k = i % 512;
        wt[k * 100 + o] = lin_w[i];
    }
    else if (idx < e5)  halo_fill(bas2, idx - e4, 18);
    else if (idx < e6)  halo_fill(bas3, idx - e5, 10);
}

// ---------------- final linear: [256,512] @ [512,100]^T + b ----------------
__global__ void __launch_bounds__(128)
linear_kernel(const float* __restrict__ X, const float* __restrict__ WT,
              const float* __restrict__ bias, float* __restrict__ out) {
    __shared__ float xs[4][512];
    int b0 = blockIdx.x * 4;
    for (int i = threadIdx.x; i < 4 * 512; i += blockDim.x)
        xs[i / 512][i % 512] = X[(long)b0 * 512 + i];
    __syncthreads();
    int o = threadIdx.x;
    if (o >= 100) return;
    float acc0 = 0.f, acc1 = 0.f, acc2 = 0.f, acc3 = 0.f;
    for (int k = 0; k < 512; k++) {
        float w = WT[k * 100 + o];
        acc0 = fmaf(xs[0][k], w, acc0);
        acc1 = fmaf(xs[1][k], w, acc1);
        acc2 = fmaf(xs[2][k], w, acc2);
        acc3 = fmaf(xs[3][k], w, acc3);
    }
    float bb = bias[o];
    out[(b0 + 0) * 100 + o] = acc0 + bb;
    out[(b0 + 1) * 100 + o] = acc1 + bb;
    out[(b0 + 2) * 100 + o] = acc2 + bb;
    out[(b0 + 3) * 100 + o] = acc3 + bb;
}

// ---------------- launch ---------------------------------------------------
extern "C" void kernel_launch(void* const* d_in, const int* in_sizes, int n_in,
                              void* d_out, int out_size) {
    const float* x     = (const float*)d_in[0];
    const float* c1_bw = (const float*)d_in[1];
    const float* c1_sw = (const float*)d_in[2];
    const float* c1_sc = (const float*)d_in[3];
    const float* c2_bw = (const float*)d_in[4];
    const float* c2_sw = (const float*)d_in[5];
    const float* c2_sc = (const float*)d_in[6];
    const float* c3_bw = (const float*)d_in[7];
    const float* c3_sw = (const float*)d_in[8];
    const float* c3_sc = (const float*)d_in[9];
    const float* lin_w = (const float*)d_in[10];
    const float* lin_b = (const float*)d_in[11];
    float* out = (float*)d_out;

    float *p_bas1, *p_bas2, *p_bas3, *p_pool3;
    float *p_sw1, *p_sw2, *p_sw3, *p_wt;
    cudaGetSymbolAddress((void**)&p_bas1,  d_bas1);
    cudaGetSymbolAddress((void**)&p_bas2,  d_bas2);
    cudaGetSymbolAddress((void**)&p_bas3,  d_bas3);
    cudaGetSymbolAddress((void**)&p_pool3, d_pool3);
    cudaGetSymbolAddress((void**)&p_sw1,   d_sw1);
    cudaGetSymbolAddress((void**)&p_sw2,   d_sw2);
    cudaGetSymbolAddress((void**)&p_sw3,   d_sw3);
    cudaGetSymbolAddress((void**)&p_wt,    d_wt);

    // prep: weights + basis halos (1 launch)
    {
        int total = 8*27*7 + 16*72*7 + 32*144*7 + 100*512
                  + BATCH*8*(4*18-4) + BATCH*16*(4*10-4);
        prep_all_kernel<<<(total + 255) / 256, 256>>>(
            c1_bw, c1_sw, c1_sc, c2_bw, c2_sw, c2_sc, c3_bw, c3_sw, c3_sc,
            lin_w, p_sw1, p_sw2, p_sw3, p_wt, p_bas2, p_bas3);
    }
    // layer-1 input basis
    {
        int n = BATCH * 3 * 34 * 34;
        basis_in_kernel<3, 32><<<(n + 255) / 256, 256>>>(x, p_bas1);
    }
    // fused conv+pool+basis layers
    {
        dim3 g1(BATCH * 32 * 16 / 256, 1);
        convpool_kernel<3, 32, 1, true ><<<g1, 256>>>(p_bas1, p_sw1, p_bas2);
        dim3 g2(BATCH * 16 * 8 / 256, 2);
        convpool_kernel<8, 16, 2, true ><<<g2, 256>>>(p_bas2, p_sw2, p_bas3);
        dim3 g3(BATCH * 8 * 4 / 256, 4);
        convpool_kernel<16, 8, 4, false><<<g3, 256>>>(p_bas3, p_sw3, p_pool3);
    }
    // linear
    linear_kernel<<<BATCH / 4, 128>>>(p_pool3, p_wt, lin_b, out);
}

// round 10
// speedup vs baseline: 1.5353x; 1.2320x over previous
#include <cuda_runtime.h>
#include <cuda_bf16.h>

#define BATCH 256

// zero-value basis constants: v=0 -> t=4.5, i0=4, u=0.5
#define ZB2 (1.f/48.f)
#define ZB3 (23.f/48.f)

typedef unsigned long long u64;

// ---------------- packed f32x2 helpers (Blackwell FFMA2) -------------------
__device__ __forceinline__ u64 pack_dup(float x) {
    u64 r; asm("mov.b64 %0, {%1, %1};" : "=l"(r) : "f"(x)); return r;
}
__device__ __forceinline__ void unpack2(u64 v, float& x, float& y) {
    asm("mov.b64 {%0, %1}, %2;" : "=f"(x), "=f"(y) : "l"(v));
}
__device__ __forceinline__ void ffma2(u64& d, u64 a, u64 b) {
    asm("fma.rn.f32x2 %0, %1, %2, %0;" : "+l"(d) : "l"(a), "l"(b));
}

// ---------------- scratch (static device globals) ---------------------------
// SoA basis: [B][C][7 slots][P rows][RP padded cols]
__device__ float d_bas1 [BATCH * 3  * 7 * 34 * 36];
__device__ float d_bas2 [BATCH * 8  * 7 * 18 * 20];
__device__ float d_bas3 [BATCH * 16 * 7 * 10 * 12];
__device__ float d_pool3[BATCH * 32 * 4 * 4];
// weights: L1 [F][7][8]; L2 [4 tiles][F][7][4]; L3 [F][7][32]
__device__ float d_sw1[27  * 7 * 8];
__device__ float d_sw2[4 * 72 * 7 * 4];
__device__ float d_sw3[144 * 7 * 32];
__device__ float d_wt [512 * 100];   // transposed lin_w: [k][o]

// ---------------- basis evaluation (7 slots) --------------------------------
__device__ __forceinline__ void basis7(float v, float* sv) {
    sv[0] = v * (1.f / (1.f + __expf(-v)));          // silu
    float t  = (v + 3.f) * 1.5f;
    bool valid = (t >= 0.f) && (t < 9.f);
    float fi = floorf(t);
    int   i0 = (int)fi;
    float u  = t - fi;
    float u2 = u * u, u3 = u2 * u;
    float q3 = u3 * (1.f / 6.f);
    float q2 = ((3.f * u2 - 3.f * u3) + 3.f * u + 1.f) * (1.f / 6.f);
    float q1 = (3.f * u3 - 6.f * u2 + 4.f) * (1.f / 6.f);
    float iu = 1.f - u;
    float q0 = iu * iu * iu * (1.f / 6.f);
    if (!valid) { q0 = q1 = q2 = q3 = 0.f; i0 = -1000; }
#pragma unroll
    for (int m = 0; m < 6; m++) {
        int d = i0 - m;
        sv[1 + m] = (d == 0) ? q3 : (d == 1) ? q2 : (d == 2) ? q1
                  : (d == 3) ? q0 : 0.f;
    }
}

// ---------------- layer-1 input basis (SoA) ---------------------------------
__global__ void basis_in_kernel(const float* __restrict__ X, float* __restrict__ BAS) {
    constexpr int P = 34, RP = 36, HW = 32;
    int idx = blockIdx.x * blockDim.x + threadIdx.x;
    if (idx >= BATCH * 3 * P * P) return;
    int xp = idx % P;
    int yp = (idx / P) % P;
    int bc = idx / (P * P);
    float sv[7];
    if (xp == 0 || xp == P - 1 || yp == 0 || yp == P - 1) {
        sv[0] = 0.f; sv[1] = 0.f; sv[2] = ZB2; sv[3] = ZB3;
        sv[4] = ZB3; sv[5] = ZB2; sv[6] = 0.f;
    } else {
        float v = X[((long)bc * HW + (yp - 1)) * HW + (xp - 1)];
        basis7(v, sv);
    }
    float* base = BAS + ((long)bc * 7 * P + yp) * RP + xp;
#pragma unroll
    for (int s = 0; s < 7; s++) base[(long)s * P * RP] = sv[s];
}

// -------- fused conv3x3 + pool + next-basis, SoA loads, POS=4 --------------
// thread = 4 x-positions, one row y, TILE output channels.
template<int C, int HW, int RPI, int TILE, int NTILE, int PO, int RPO, bool WB>
__global__ void __launch_bounds__(256)
convpool_soa(const float* __restrict__ BAS,   // [B][C][7][P][RPI]
             const float* __restrict__ SW,    // [NTILE][F][7][TILE]
             float* __restrict__ OUT) {
    constexpr int F   = C * 9;
    constexpr int P   = HW + 2;
    constexpr int HX4 = HW / 4;
    constexpr int OC  = NTILE * TILE;
    constexpr int NP  = TILE / 2;
    __shared__ __align__(16) float sw[F * 7 * TILE];

    const float* gsw = SW + blockIdx.y * (F * 7 * TILE);
    for (int i = threadIdx.x; i < F * 7 * TILE / 4; i += 256)
        reinterpret_cast<float4*>(sw)[i] = reinterpret_cast<const float4*>(gsw)[i];
    __syncthreads();

    int p  = blockIdx.x * 256 + threadIdx.x;
    int k  = p % HX4;
    int y  = (p / HX4) % HW;
    int b  = p / (HX4 * HW);
    int x0 = 4 * k;

    u64 acc2[4][NP];
#pragma unroll
    for (int pos = 0; pos < 4; pos++)
#pragma unroll
        for (int q = 0; q < NP; q++) acc2[pos][q] = 0ull;

    for (int c = 0; c < C; c++) {
        const float* Bc = BAS + (long)(b * C + c) * 7 * P * RPI;
#pragma unroll
        for (int ky = 0; ky < 3; ky++) {
            float bv[7][6];
#pragma unroll
            for (int s = 0; s < 7; s++) {
                const float* q = Bc + ((long)s * P + (y + ky)) * RPI + x0;
                float4 a = *reinterpret_cast<const float4*>(q);
                float2 e = *reinterpret_cast<const float2*>(q + 4);
                bv[s][0] = a.x; bv[s][1] = a.y; bv[s][2] = a.z;
                bv[s][3] = a.w; bv[s][4] = e.x; bv[s][5] = e.y;
            }
            const float* wbase = sw + (c * 9 + ky * 3) * 7 * TILE;
#pragma unroll
            for (int kx = 0; kx < 3; kx++) {
#pragma unroll
                for (int s = 0; s < 7; s++) {
                    const float* wp = wbase + (kx * 7 + s) * TILE;
                    ulonglong2 wA = *reinterpret_cast<const ulonglong2*>(wp);
                    ulonglong2 wB;
                    if (TILE == 8) wB = *reinterpret_cast<const ulonglong2*>(wp + 4);
#pragma unroll
                    for (int pos = 0; pos < 4; pos++) {
                        u64 sp = pack_dup(bv[s][kx + pos]);
                        ffma2(acc2[pos][0], sp, wA.x);
                        if (NP > 1) ffma2(acc2[pos][1], sp, wA.y);
                        if (TILE == 8) {
                            ffma2(acc2[pos][2], sp, wB.x);
                            ffma2(acc2[pos][3], sp, wB.y);
                        }
                    }
                }
            }
        }
    }

    // horizontal pool (pos pairs), then vertical via shfl partner row y^1
    float hm[2][TILE];
#pragma unroll
    for (int q = 0; q < NP; q++) {
#pragma unroll
        for (int xl = 0; xl < 2; xl++) {
            float a0, a1, b0, b1;
            unpack2(acc2[2 * xl][q],     a0, a1);
            unpack2(acc2[2 * xl + 1][q], b0, b1);
            hm[xl][2 * q]     = fmaxf(a0, b0);
            hm[xl][2 * q + 1] = fmaxf(a1, b1);
        }
    }
#pragma unroll
    for (int xl = 0; xl < 2; xl++)
#pragma unroll
        for (int j = 0; j < TILE; j++) {
            float o = __shfl_xor_sync(0xffffffffu, hm[xl][j], HX4);
            hm[xl][j] = fmaxf(hm[xl][j], o);
        }

    if (((p / HX4) & 1) == 0) {
        int xo0 = 2 * k;
        int yo  = y >> 1;
        if (WB) {
#pragma unroll
            for (int j = 0; j < TILE; j++)
#pragma unroll
                for (int xl = 0; xl < 2; xl++) {
                    float sv[7];
                    basis7(hm[xl][j], sv);
                    int ch = blockIdx.y * TILE + j;
                    float* base = OUT + (((long)(b * OC + ch) * 7) * PO + (yo + 1)) * RPO
                                      + (xo0 + xl + 1);
#pragma unroll
                    for (int s = 0; s < 7; s++) base[(long)s * PO * RPO] = sv[s];
                }
        }
    }
}

// -------- layer-3: smem-staged conv + pool (all 32 channels per block) ------
// block = half image (4 conv rows), 64 threads = 4 rows x 16 channel-tiles.
__global__ void __launch_bounds__(64)
convpool3_kernel(const float* __restrict__ BAS,   // [B][16][7][10][12]
                 const float* __restrict__ SW,    // [144][7][32]
                 float* __restrict__ OUTP) {      // [B][32][4][4]
    constexpr int P = 10, RP = 12, ROWS = 6;
    __shared__ __align__(16) float tile[8 * 7 * ROWS * RP];   // 16128 B

    int tid = threadIdx.x;
    int r   = tid & 3;          // conv row within half
    int tl  = tid >> 2;         // channel tile 0..15 (2 ch each)
    int b   = blockIdx.x >> 1;
    int y0  = (blockIdx.x & 1) * 4;

    u64 acc2[8];
#pragma unroll
    for (int pos = 0; pos < 8; pos++) acc2[pos] = 0ull;

    for (int ph = 0; ph < 2; ph++) {
        __syncthreads();
        // stage 8 channels x 7 slots x 6 rows x 12 cols
        for (int i = tid; i < 8 * 7 * 18; i += 64) {
            int cs = i / 18, rr = i % 18;
            const float4* src = reinterpret_cast<const float4*>(
                BAS + ((long)((b * 16 + ph * 8 + cs / 7) * 7 + cs % 7) * P + y0) * RP) + rr;
            reinterpret_cast<float4*>(tile)[cs * 18 + rr] = *src;
        }
        __syncthreads();

        for (int cl = 0; cl < 8; cl++) {
#pragma unroll
            for (int ky = 0; ky < 3; ky++) {
                float bv[7][10];
#pragma unroll
                for (int s = 0; s < 7; s++) {
                    const float* q = tile + ((cl * 7 + s) * ROWS + (r + ky)) * RP;
                    float4 a = *reinterpret_cast<const float4*>(q);
                    float4 d = *reinterpret_cast<const float4*>(q + 4);
                    float2 e = *reinterpret_cast<const float2*>(q + 8);
                    bv[s][0] = a.x; bv[s][1] = a.y; bv[s][2] = a.z; bv[s][3] = a.w;
                    bv[s][4] = d.x; bv[s][5] = d.y; bv[s][6] = d.z; bv[s][7] = d.w;
                    bv[s][8] = e.x; bv[s][9] = e.y;
                }
                const float* wb = SW + ((long)((ph * 8 + cl) * 9 + ky * 3) * 7) * 32 + tl * 2;
#pragma unroll
                for (int kx = 0; kx < 3; kx++) {
#pragma unroll
                    for (int s = 0; s < 7; s++) {
                        u64 w = *reinterpret_cast<const u64*>(wb + (kx * 7 + s) * 32);
#pragma unroll
                        for (int pos = 0; pos < 8; pos++) {
                            u64 sp = pack_dup(bv[s][kx + pos]);
                            ffma2(acc2[pos], sp, w);
                        }
                    }
                }
            }
        }
    }

    // pool: horizontal pairs then vertical shfl (partner row r^1 = lane^1)
    float hm[4][2];
#pragma unroll
    for (int xo = 0; xo < 4; xo++) {
        float a0, a1, b0, b1;
        unpack2(acc2[2 * xo],     a0, a1);
        unpack2(acc2[2 * xo + 1], b0, b1);
        hm[xo][0] = fmaxf(a0, b0);
        hm[xo][1] = fmaxf(a1, b1);
    }
#pragma unroll
    for (int xo = 0; xo < 4; xo++)
#pragma unroll
        for (int j = 0; j < 2; j++) {
            float o = __shfl_xor_sync(0xffffffffu, hm[xo][j], 1);
            hm[xo][j] = fmaxf(hm[xo][j], o);
        }

    if ((r & 1) == 0) {
        int yo = (y0 + r) >> 1;
#pragma unroll
        for (int j = 0; j < 2; j++) {
            int ch = tl * 2 + j;
            float4 v = make_float4(hm[0][j], hm[1][j], hm[2][j], hm[3][j]);
            *reinterpret_cast<float4*>(OUTP + (((long)b * 32 + ch) * 4 + yo) * 4) = v;
        }
    }
}

// ---------------- merged weight prep + SoA halo fill ------------------------
__device__ __forceinline__ float sw_val(const float* bw, const float* sp,
                                        const float* sc, int o, int f, int slot, int F) {
    if (slot == 0) return bw[o * F + f];
    return sp[(o * F + f) * 6 + (slot - 1)] * sc[o * F + f];
}

__device__ __forceinline__ void halo_fill(float* bas, int i, int P, int RP) {
    int hc  = 4 * P - 4;
    int img = i / hc;
    int kk  = i % hc;
    int xp, yp;
    if (kk < P)          { yp = 0;      xp = kk; }
    else if (kk < 2 * P) { yp = P - 1;  xp = kk - P; }
    else {
        int rr = kk - 2 * P;
        yp = 1 + (rr >> 1);
        xp = (rr & 1) ? (P - 1) : 0;
    }
    const float zb[7] = {0.f, 0.f, ZB2, ZB3, ZB3, ZB2, 0.f};
    float* base = bas + ((long)img * 7 * P + yp) * RP + xp;
#pragma unroll
    for (int s = 0; s < 7; s++) base[(long)s * P * RP] = zb[s];
}

__global__ void prep_all_kernel(const float* __restrict__ c1_bw, const float* __restrict__ c1_sw,
                                const float* __restrict__ c1_sc,
                                const float* __restrict__ c2_bw, const float* __restrict__ c2_sw,
                                const float* __restrict__ c2_sc,
                                const float* __restrict__ c3_bw, const float* __restrict__ c3_sw,
                                const float* __restrict__ c3_sc,
                                const float* __restrict__ lin_w,
                                float* __restrict__ sw1, float* __restrict__ sw2,
                                float* __restrict__ sw3, float* __restrict__ wt,
                                float* __restrict__ bas2, float* __restrict__ bas3) {
    const int N1 = 8 * 27 * 7, N2 = 16 * 72 * 7, N3 = 32 * 144 * 7, NW = 100 * 512;
    const int H2 = BATCH * 8 * (4 * 18 - 4);
    const int H3 = BATCH * 16 * (4 * 10 - 4);
    int idx = blockIdx.x * blockDim.x + threadIdx.x;
    int e1 = N1, e2 = e1 + N2, e3 = e2 + N3, e4 = e3 + NW, e5 = e4 + H2, e6 = e5 + H3;
    if (idx < e1) {
        int slot = idx % 7, f = (idx / 7) % 27, o = idx / (7 * 27);
        sw1[(f * 7 + slot) * 8 + o] = sw_val(c1_bw, c1_sw, c1_sc, o, f, slot, 27);
    } else if (idx < e2) {
        int i = idx - e1;
        int slot = i % 7, f = (i / 7) % 72, o = i / (7 * 72);
        sw2[(((o >> 2) * 72 + f) * 7 + slot) * 4 + (o & 3)] =
            sw_val(c2_bw, c2_sw, c2_sc, o, f, slot, 72);
    } else if (idx < e3) {
        int i = idx - e2;
        int slot = i % 7, f = (i / 7) % 144, o = i / (7 * 144);
        sw3[(f * 7 + slot) * 32 + o] = sw_val(c3_bw, c3_sw, c3_sc, o, f, slot, 144);
    } else if (idx < e4) {
        int i = idx - e3;
        int o = i / 512, k = i % 512;
        wt[k * 100 + o] = lin_w[i];
    } else if (idx < e5) halo_fill(bas2, idx - e4, 18, 20);
    else if (idx < e6)   halo_fill(bas3, idx - e5, 10, 12);
}

// ---------------- final linear: [256,512] @ [512,100]^T + b -----------------
__global__ void __launch_bounds__(128)
linear_kernel(const float* __restrict__ X, const float* __restrict__ WT,
              const float* __restrict__ bias, float* __restrict__ out) {
    __shared__ float xs[4][512];
    int b0 = blockIdx.x * 4;
    for (int i = threadIdx.x; i < 4 * 512; i += blockDim.x)
        xs[i / 512][i % 512] = X[(long)b0 * 512 + i];
    __syncthreads();
    int o = threadIdx.x;
    if (o >= 100) return;
    float acc0 = 0.f, acc1 = 0.f, acc2 = 0.f, acc3 = 0.f;
    for (int k = 0; k < 512; k++) {
        float w = WT[k * 100 + o];
        acc0 = fmaf(xs[0][k], w, acc0);
        acc1 = fmaf(xs[1][k], w, acc1);
        acc2 = fmaf(xs[2][k], w, acc2);
        acc3 = fmaf(xs[3][k], w, acc3);
    }
    float bb = bias[o];
    out[(b0 + 0) * 100 + o] = acc0 + bb;
    out[(b0 + 1) * 100 + o] = acc1 + bb;
    out[(b0 + 2) * 100 + o] = acc2 + bb;
    out[(b0 + 3) * 100 + o] = acc3 + bb;
}

// ---------------- launch ----------------------------------------------------
extern "C" void kernel_launch(void* const* d_in, const int* in_sizes, int n_in,
                              void* d_out, int out_size) {
    const float* x     = (const float*)d_in[0];
    const float* c1_bw = (const float*)d_in[1];
    const float* c1_sw = (const float*)d_in[2];
    const float* c1_sc = (const float*)d_in[3];
    const float* c2_bw = (const float*)d_in[4];
    const float* c2_sw = (const float*)d_in[5];
    const float* c2_sc = (const float*)d_in[6];
    const float* c3_bw = (const float*)d_in[7];
    const float* c3_sw = (const float*)d_in[8];
    const float* c3_sc = (const float*)d_in[9];
    const float* lin_w = (const float*)d_in[10];
    const float* lin_b = (const float*)d_in[11];
    float* out = (float*)d_out;

    float *p_bas1, *p_bas2, *p_bas3, *p_pool3;
    float *p_sw1, *p_sw2, *p_sw3, *p_wt;
    cudaGetSymbolAddress((void**)&p_bas1,  d_bas1);
    cudaGetSymbolAddress((void**)&p_bas2,  d_bas2);
    cudaGetSymbolAddress((void**)&p_bas3,  d_bas3);
    cudaGetSymbolAddress((void**)&p_pool3, d_pool3);
    cudaGetSymbolAddress((void**)&p_sw1,   d_sw1);
    cudaGetSymbolAddress((void**)&p_sw2,   d_sw2);
    cudaGetSymbolAddress((void**)&p_sw3,   d_sw3);
    cudaGetSymbolAddress((void**)&p_wt,    d_wt);

    // prep: weights + SoA halos
    {
        int total = 8*27*7 + 16*72*7 + 32*144*7 + 100*512
                  + BATCH*8*(4*18-4) + BATCH*16*(4*10-4);
        prep_all_kernel<<<(total + 255) / 256, 256>>>(
            c1_bw, c1_sw, c1_sc, c2_bw, c2_sw, c2_sc, c3_bw, c3_sw, c3_sc,
            lin_w, p_sw1, p_sw2, p_sw3, p_wt, p_bas2, p_bas3);
    }
    // layer-1 input basis
    {
        int n = BATCH * 3 * 34 * 34;
        basis_in_kernel<<<(n + 255) / 256, 256>>>(x, p_bas1);
    }
    // L1: C=3 HW=32 RPI=36 TILE=8 NTILE=1 -> bas2 (PO=18, RPO=20)
    {
        dim3 g(BATCH * 32 * 8 / 256, 1);
        convpool_soa<3, 32, 36, 8, 1, 18, 20, true><<<g, 256>>>(p_bas1, p_sw1, p_bas2);
    }
    // L2: C=8 HW=16 RPI=20 TILE=4 NTILE=4 -> bas3 (PO=10, RPO=12)
    {
        dim3 g(BATCH * 16 * 4 / 256, 4);
        convpool_soa<8, 16, 20, 4, 4, 10, 12, true><<<g, 256>>>(p_bas2, p_sw2, p_bas3);
    }
    // L3: smem-staged, all 32 channels per block
    {
        convpool3_kernel<<<BATCH * 2, 64>>>(p_bas3, p_sw3, p_pool3);
    }
    // linear
    linear_kernel<<<BATCH / 4, 128>>>(p_pool3, p_wt, lin_b, out);
}